// round 13
// baseline (speedup 1.0000x reference)
#include <cuda_runtime.h>
#include <cuda_bf16.h>
#include <math.h>

#define N_MAX 50000
#define E_MAX 200000
#define TILE_N 32
#define CAP 40   // max in-degree slots per node (Poisson(4): P(>40) ~ 1e-38)

// Device scratch (no allocation allowed; zero-initialized at load,
// re-zeroed by fused_kernel at the end of every run => replay-safe)
__device__ int    g_cnt[N_MAX];
__device__ int    g_slot_send[N_MAX * CAP];     // 8 MB
__device__ float4 g_slot_sh[N_MAX * CAP];       // 32 MB
__device__ float  g_wc[2 * 96 * 32];            // combined weights [ch][k][v]

// --------------------------------------------------------------------------
// Kernel 1: direct slot scatter + combined-weight prep (merged).
// Edge e: pos = atomicAdd(cnt[recv]); record -> slot[recv*CAP + pos].
// Threads idx < 6144 additionally build the combined weights:
//   ch0:   w[k][v] = W0[k][v]/(1.5*sqrt(96)) + (k<32 ? Ws0[k][v]/sqrt(32) : 0)
//   chvec: w[k][v] = W1[k][v]/(1.5*sqrt(96)) + (k<32 ? Ws1[k][v]/sqrt(32) : 0)
// --------------------------------------------------------------------------
__global__ void scatter_wprep_kernel(const int* __restrict__ send,
                                     const int* __restrict__ recv,
                                     const float* __restrict__ sh, int E,
                                     const float* __restrict__ W0,
                                     const float* __restrict__ W1,
                                     const float* __restrict__ Ws0,
                                     const float* __restrict__ Ws1) {
    int idx = blockIdx.x * blockDim.x + threadIdx.x;

    if (idx < 2 * 96 * 32) {
        const float c1 = 1.0f / (1.5f * 9.79795897113271f);  // 1/(1.5*sqrt(96))
        const float c2 = 1.0f / 5.656854249492381f;           // 1/sqrt(32)
        int ch = idx / (96 * 32);
        int rr = idx - ch * (96 * 32);
        int k = rr >> 5;
        const float* W  = ch ? W1  : W0;
        const float* Ws = ch ? Ws1 : Ws0;
        float val = W[rr] * c1;
        if (k < 32) val += Ws[rr] * c2;
        g_wc[idx] = val;
    }

    if (idx < E) {
        int r = recv[idx];
        if (r >= 0 && r < N_MAX) {
            int pos = atomicAdd(&g_cnt[r], 1);
            if (pos >= 0 && pos < CAP) {
                g_slot_send[r * CAP + pos] = send[idx];
                g_slot_sh[r * CAP + pos] =
                    __ldg(reinterpret_cast<const float4*>(sh) + idx);
            }
        }
    }
}

// --------------------------------------------------------------------------
// Kernel 2: fused gather + GEMM, 256 threads/block (2x occupancy vs R11).
// Block handles TILE_N=32 nodes (all 4 output groups = 128 output rows).
// Phase 1 (gather): 8 warps, warp w owns nodes w*4..w*4+3; per node iterate
//   its slots (deg = clamp(g_cnt[node])), accumulate 12 TP chains in
//   registers, store to swizzled smem Xs[k][row]:
//     row = g*32+m (g=0 scalar, 1..3 = x/y/z), k = chain*32+u
//     chains: g0 [f0, s0*f0, dot/sqrt3]; g(1+c) [f1c, s0*f1c, f0*s1c]
//   XIDX(k,row) = k*128 + (row ^ ((k&7)<<2)) — GEMM loads conflict-free.
// Phase 2 (GEMM): 256 threads, thread tile 2 rows x 8 cols; plain FFMA
//   (NO f32x2 — packed-PTX kernels kill this container, 0/3).
//   out[row][v] = (1/cnt) * sum_k Xs[k][row]*W_g[k][v], W via __ldg.
// Tail: t<32 zeroes g_cnt[node] after syncthreads (replay-safe).
// Static smem = exactly 48KB (Xs only) -> 4 blocks/SM, 32 warps/SM.
// --------------------------------------------------------------------------
__global__ void __launch_bounds__(256) fused_kernel(const float* __restrict__ nf,
                                                    float* __restrict__ out,
                                                    int n_nodes) {
    __shared__ float Xs[96 * 128];   // exactly 48KB
    const float INV_SQRT3 = 0.57735026918962576f;

    int t = threadIdx.x;
    int lane = t & 31;
    int w = t >> 5;               // 0..7
    int nodeBase = blockIdx.x * TILE_N;

    // ---- gather phase: 8 warps x 4 nodes ----
    #pragma unroll 1
    for (int mi = 0; mi < 4; mi++) {
        int m = w * 4 + mi;
        int i = nodeBase + m;
        if (i >= n_nodes) break;
        int deg = __ldg(g_cnt + i);
        deg = max(0, min(deg, CAP));

        float a0 = 0.f, a1 = 0.f, a2 = 0.f;   // g0: f0, s0*f0, dot
        float b0 = 0.f, b1 = 0.f, b2 = 0.f;   // gx: f1x, s0*f1x, f0*s1x
        float c0 = 0.f, c1 = 0.f, c2 = 0.f;   // gy
        float d0 = 0.f, d1 = 0.f, d2 = 0.f;   // gz

        const int*    slotS = g_slot_send + (size_t)i * CAP;
        const float4* slotH = g_slot_sh   + (size_t)i * CAP;

        for (int e = 0; e < deg; e++) {
            int s = __ldg(slotS + e);
            float4 shv = __ldg(slotH + e);
            const float* nfr = nf + 128 * s;
            float f0  = __ldg(nfr + lane);
            float f1x = __ldg(nfr + 32 + 3 * lane);
            float f1y = __ldg(nfr + 33 + 3 * lane);
            float f1z = __ldg(nfr + 34 + 3 * lane);

            a0 += f0;
            a1 = fmaf(shv.x, f0, a1);
            a2 += shv.y * f1x + shv.z * f1y + shv.w * f1z;
            b0 += f1x; b1 = fmaf(shv.x, f1x, b1); b2 = fmaf(f0, shv.y, b2);
            c0 += f1y; c1 = fmaf(shv.x, f1y, c1); c2 = fmaf(f0, shv.z, c2);
            d0 += f1z; d1 = fmaf(shv.x, f1z, d1); d2 = fmaf(f0, shv.w, d2);
        }
        a2 *= INV_SQRT3;

        // swizzled stores: c = (k&7)<<2, same for all 3 chains (k≡lane mod 32)
        int mc = m ^ ((lane & 7) << 2);
        float* X0 = Xs + lane * 128;          // chain0: k=lane
        X0[mc] = a0; X0[32 + mc] = b0; X0[64 + mc] = c0; X0[96 + mc] = d0;
        float* X1 = Xs + (32 + lane) * 128;   // chain1: k=32+lane
        X1[mc] = a1; X1[32 + mc] = b1; X1[64 + mc] = c1; X1[96 + mc] = d1;
        float* X2 = Xs + (64 + lane) * 128;   // chain2: k=64+lane
        X2[mc] = a2; X2[32 + mc] = b2; X2[64 + mc] = c2; X2[96 + mc] = d2;
    }
    __syncthreads();

    // ---- GEMM phase: thread tile 2 rows x 8 cols ----
    int tx = t & 3;
    int ty = t >> 2;              // 0..63
    int row0 = ty * 2;            // even
    const float* Wp = g_wc + ((row0 < 32) ? 0 : 96 * 32);

    float acc[2][8];
    #pragma unroll
    for (int j = 0; j < 2; j++)
        #pragma unroll
        for (int q = 0; q < 8; q++) acc[j][q] = 0.f;

    #pragma unroll 4
    for (int k = 0; k < 96; k++) {
        // row0 even, swizzle c multiple of 4 => (row0^c) even, float2 aligned
        float2 x = *reinterpret_cast<const float2*>(
            &Xs[k * 128 + (row0 ^ ((k & 7) << 2))]);
        float4 wa = __ldg(reinterpret_cast<const float4*>(Wp + k * 32 + tx * 4));
        float4 wb = __ldg(reinterpret_cast<const float4*>(Wp + k * 32 + 16 + tx * 4));
        acc[0][0] = fmaf(x.x, wa.x, acc[0][0]);
        acc[0][1] = fmaf(x.x, wa.y, acc[0][1]);
        acc[0][2] = fmaf(x.x, wa.z, acc[0][2]);
        acc[0][3] = fmaf(x.x, wa.w, acc[0][3]);
        acc[0][4] = fmaf(x.x, wb.x, acc[0][4]);
        acc[0][5] = fmaf(x.x, wb.y, acc[0][5]);
        acc[0][6] = fmaf(x.x, wb.z, acc[0][6]);
        acc[0][7] = fmaf(x.x, wb.w, acc[0][7]);
        acc[1][0] = fmaf(x.y, wa.x, acc[1][0]);
        acc[1][1] = fmaf(x.y, wa.y, acc[1][1]);
        acc[1][2] = fmaf(x.y, wa.z, acc[1][2]);
        acc[1][3] = fmaf(x.y, wa.w, acc[1][3]);
        acc[1][4] = fmaf(x.y, wb.x, acc[1][4]);
        acc[1][5] = fmaf(x.y, wb.y, acc[1][5]);
        acc[1][6] = fmaf(x.y, wb.z, acc[1][6]);
        acc[1][7] = fmaf(x.y, wb.w, acc[1][7]);
    }

    // ---- epilogue ----
    #pragma unroll
    for (int j = 0; j < 2; j++) {
        int row = row0 + j;
        int g = row >> 5;
        int m = row & 31;
        int node = nodeBase + m;
        if (node >= n_nodes) continue;
        int cnt = __ldg(g_cnt + node);
        cnt = max(0, min(cnt, CAP));
        float iv = (cnt > 0) ? __fdividef(1.0f, (float)cnt) : 1.0f;
        size_t ob = (size_t)node * 128;
        if (g == 0) {
            *reinterpret_cast<float4*>(&out[ob + tx * 4]) =
                make_float4(acc[j][0] * iv, acc[j][1] * iv,
                            acc[j][2] * iv, acc[j][3] * iv);
            *reinterpret_cast<float4*>(&out[ob + 16 + tx * 4]) =
                make_float4(acc[j][4] * iv, acc[j][5] * iv,
                            acc[j][6] * iv, acc[j][7] * iv);
        } else {
            int b = 32 + (g - 1);
            #pragma unroll
            for (int q = 0; q < 8; q++) {
                int v = (q < 4) ? (tx * 4 + q) : (16 + tx * 4 + (q - 4));
                out[ob + b + 3 * v] = acc[j][q] * iv;
            }
        }
    }

    // ---- tail: self-clean counts for next graph replay ----
    __syncthreads();
    if (t < TILE_N) {
        int node = nodeBase + t;
        if (node < n_nodes) g_cnt[node] = 0;
    }
}

// --------------------------------------------------------------------------
// Launcher — exactly 2 kernels
// --------------------------------------------------------------------------
extern "C" void kernel_launch(void* const* d_in, const int* in_sizes, int n_in,
                              void* d_out, int out_size) {
    const float* nf   = (const float*)d_in[0];   // [N,128]
    const float* sh   = (const float*)d_in[1];   // [E,4]
    const int* senders   = (const int*)d_in[2];  // [E]
    const int* receivers = (const int*)d_in[3];  // [E]
    const float* W0  = (const float*)d_in[4];    // [96,32]
    const float* W1  = (const float*)d_in[5];    // [96,32]
    const float* Ws0 = (const float*)d_in[6];    // [32,32]
    const float* Ws1 = (const float*)d_in[7];    // [32,32]
    float* out = (float*)d_out;

    int n_nodes = in_sizes[0] / 128;
    int E = in_sizes[2];

    scatter_wprep_kernel<<<(E + 255) / 256, 256>>>(senders, receivers, sh, E,
                                                   W0, W1, Ws0, Ws1);

    int fb = (n_nodes + TILE_N - 1) / TILE_N;
    fused_kernel<<<fb, 256>>>(nf, out, n_nodes);
}

// round 15
// speedup vs baseline: 1.2765x; 1.2765x over previous
#include <cuda_runtime.h>
#include <cuda_bf16.h>
#include <cstdint>
#include <math.h>

#define N_MAX 50000
#define E_MAX 200000
#define TILE_N 32
#define CAP 40   // max in-degree slots per node (Poisson(4): P(>40) ~ 1e-38)

// Device scratch (no allocation allowed; zero-initialized at load,
// re-zeroed by fused_kernel at the end of every run => replay-safe)
__device__ int    g_cnt[N_MAX];
__device__ int    g_slot_send[N_MAX * CAP];     // 8 MB
__device__ float4 g_slot_sh[N_MAX * CAP];       // 32 MB
__device__ float  g_wc[2 * 96 * 32];            // combined weights [ch][k][v]

// m16n8k8 tf32 mma, row.col, fp32 accumulate
#define MMA_TF32(c, a, b) \
    asm("mma.sync.aligned.m16n8k8.row.col.f32.tf32.tf32.f32 " \
        "{%0,%1,%2,%3}, {%4,%5,%6,%7}, {%8,%9}, {%0,%1,%2,%3};" \
        : "+f"((c)[0]), "+f"((c)[1]), "+f"((c)[2]), "+f"((c)[3]) \
        : "r"((a)[0]), "r"((a)[1]), "r"((a)[2]), "r"((a)[3]), \
          "r"((b)[0]), "r"((b)[1]))

__device__ __forceinline__ void split_tf32(float x, uint32_t& hi, uint32_t& lo) {
    asm("cvt.rna.tf32.f32 %0, %1;" : "=r"(hi) : "f"(x));
    float r = x - __uint_as_float(hi);
    asm("cvt.rna.tf32.f32 %0, %1;" : "=r"(lo) : "f"(r));
}

// --------------------------------------------------------------------------
// Kernel 1: direct slot scatter + combined-weight prep (merged).
// Edge e: pos = atomicAdd(cnt[recv]); record -> slot[recv*CAP + pos].
// Threads idx < 6144 additionally build the combined weights:
//   ch0:   w[k][v] = W0[k][v]/(1.5*sqrt(96)) + (k<32 ? Ws0[k][v]/sqrt(32) : 0)
//   chvec: w[k][v] = W1[k][v]/(1.5*sqrt(96)) + (k<32 ? Ws1[k][v]/sqrt(32) : 0)
// --------------------------------------------------------------------------
__global__ void scatter_wprep_kernel(const int* __restrict__ send,
                                     const int* __restrict__ recv,
                                     const float* __restrict__ sh, int E,
                                     const float* __restrict__ W0,
                                     const float* __restrict__ W1,
                                     const float* __restrict__ Ws0,
                                     const float* __restrict__ Ws1) {
    int idx = blockIdx.x * blockDim.x + threadIdx.x;

    if (idx < 2 * 96 * 32) {
        const float c1 = 1.0f / (1.5f * 9.79795897113271f);  // 1/(1.5*sqrt(96))
        const float c2 = 1.0f / 5.656854249492381f;           // 1/sqrt(32)
        int ch = idx / (96 * 32);
        int rr = idx - ch * (96 * 32);
        int k = rr >> 5;
        const float* W  = ch ? W1  : W0;
        const float* Ws = ch ? Ws1 : Ws0;
        float val = W[rr] * c1;
        if (k < 32) val += Ws[rr] * c2;
        g_wc[idx] = val;
    }

    if (idx < E) {
        int r = recv[idx];
        if (r >= 0 && r < N_MAX) {
            int pos = atomicAdd(&g_cnt[r], 1);
            if (pos >= 0 && pos < CAP) {
                g_slot_send[r * CAP + pos] = send[idx];
                g_slot_sh[r * CAP + pos] =
                    __ldg(reinterpret_cast<const float4*>(sh) + idx);
            }
        }
    }
}

// --------------------------------------------------------------------------
// Kernel 2: fused gather + tensor-core GEMM. 128 threads, TILE_N=32 nodes.
// Phase 1 (gather, identical to R11 best): warp w owns nodes w*8..w*8+7;
//   per node iterate slots (deg = clamp(g_cnt)), accumulate 12 TP chains,
//   store to swizzled smem Xs[k][row]:
//     row = g*32+m (g=0 scalar, 1..3 = x/y/z), k = chain*32+u
//     chains: g0 [f0, s0*f0, dot/sqrt3]; g(1+c) [f1c, s0*f1c, f0*s1c]
//   index = k*128 + (row ^ ((k&7)<<2)).
// Phase 2 (GEMM): 3xTF32 mma.sync m16n8k8. Warp w owns rows w*32..w*32+31
//   (group g == w). 2 row-tiles x 4 n-tiles x 12 k-steps, A from swizzled
//   smem (scalar LDS), B from g_wc via __ldg. D = Ah*Bh + Al*Bh + Ah*Bl
//   (~fp32 precision). out[row][v] = (1/cnt)*D.
// Tail: t<32 zeroes g_cnt[node] (replay-safe). Static smem = exactly 48KB.
// --------------------------------------------------------------------------
__global__ void __launch_bounds__(128) fused_kernel(const float* __restrict__ nf,
                                                    float* __restrict__ out,
                                                    int n_nodes) {
    __shared__ float Xs[96 * 128];   // exactly 48KB
    const float INV_SQRT3 = 0.57735026918962576f;

    int t = threadIdx.x;
    int lane = t & 31;
    int w = t >> 5;               // 0..3
    int nodeBase = blockIdx.x * TILE_N;

    // ---- gather phase (R11) ----
    #pragma unroll 1
    for (int mi = 0; mi < 8; mi++) {
        int m = w * 8 + mi;
        int i = nodeBase + m;
        if (i >= n_nodes) break;
        int deg = __ldg(g_cnt + i);
        deg = max(0, min(deg, CAP));

        float a0 = 0.f, a1 = 0.f, a2 = 0.f;   // g0: f0, s0*f0, dot
        float b0 = 0.f, b1 = 0.f, b2 = 0.f;   // gx: f1x, s0*f1x, f0*s1x
        float c0 = 0.f, c1 = 0.f, c2 = 0.f;   // gy
        float d0 = 0.f, d1 = 0.f, d2 = 0.f;   // gz

        const int*    slotS = g_slot_send + (size_t)i * CAP;
        const float4* slotH = g_slot_sh   + (size_t)i * CAP;

        for (int e = 0; e < deg; e++) {
            int s = __ldg(slotS + e);
            float4 shv = __ldg(slotH + e);
            const float* nfr = nf + 128 * s;
            float f0  = __ldg(nfr + lane);
            float f1x = __ldg(nfr + 32 + 3 * lane);
            float f1y = __ldg(nfr + 33 + 3 * lane);
            float f1z = __ldg(nfr + 34 + 3 * lane);

            a0 += f0;
            a1 = fmaf(shv.x, f0, a1);
            a2 += shv.y * f1x + shv.z * f1y + shv.w * f1z;
            b0 += f1x; b1 = fmaf(shv.x, f1x, b1); b2 = fmaf(f0, shv.y, b2);
            c0 += f1y; c1 = fmaf(shv.x, f1y, c1); c2 = fmaf(f0, shv.z, c2);
            d0 += f1z; d1 = fmaf(shv.x, f1z, d1); d2 = fmaf(f0, shv.w, d2);
        }
        a2 *= INV_SQRT3;

        // swizzled stores: c = (k&7)<<2, same for all 3 chains (k≡lane mod 32)
        int mc = m ^ ((lane & 7) << 2);
        float* X0 = Xs + lane * 128;          // chain0: k=lane
        X0[mc] = a0; X0[32 + mc] = b0; X0[64 + mc] = c0; X0[96 + mc] = d0;
        float* X1 = Xs + (32 + lane) * 128;   // chain1: k=32+lane
        X1[mc] = a1; X1[32 + mc] = b1; X1[64 + mc] = c1; X1[96 + mc] = d1;
        float* X2 = Xs + (64 + lane) * 128;   // chain2: k=64+lane
        X2[mc] = a2; X2[32 + mc] = b2; X2[64 + mc] = c2; X2[96 + mc] = d2;
    }
    __syncthreads();

    // ---- GEMM phase: 3xTF32 mma ----
    const float* Wp = g_wc + ((w == 0) ? 0 : 96 * 32);
    int lr = lane >> 2;   // 0..7
    int lc = lane & 3;    // 0..3

    float acc[2][4][4];
    #pragma unroll
    for (int rt = 0; rt < 2; rt++)
        #pragma unroll
        for (int nt = 0; nt < 4; nt++)
            #pragma unroll
            for (int q = 0; q < 4; q++) acc[rt][nt][q] = 0.f;

    #pragma unroll 2
    for (int ks = 0; ks < 12; ks++) {
        int k0 = ks * 8;
        // A fragments: m16n8k8 row-major layout
        //  a_j: row = base + lr + (j&1)*8, k = k0 + lc + (j>>1)*4
        uint32_t ahi[2][4], alo[2][4];
        #pragma unroll
        for (int rt = 0; rt < 2; rt++) {
            #pragma unroll
            for (int j = 0; j < 4; j++) {
                int row = w * 32 + rt * 16 + lr + (j & 1) * 8;
                int k = k0 + lc + (j >> 1) * 4;
                float x = Xs[k * 128 + (row ^ ((k & 7) << 2))];
                split_tf32(x, ahi[rt][j], alo[rt][j]);
            }
        }
        #pragma unroll
        for (int nt = 0; nt < 4; nt++) {
            // B fragment: col-major 8x8: b_j: krow = k0 + lc + j*4, col = nt*8 + lr
            uint32_t bhi[2], blo[2];
            #pragma unroll
            for (int j = 0; j < 2; j++) {
                int krow = k0 + lc + j * 4;
                float v = __ldg(Wp + krow * 32 + nt * 8 + lr);
                split_tf32(v, bhi[j], blo[j]);
            }
            #pragma unroll
            for (int rt = 0; rt < 2; rt++) {
                MMA_TF32(acc[rt][nt], ahi[rt], bhi);
                MMA_TF32(acc[rt][nt], alo[rt], bhi);
                MMA_TF32(acc[rt][nt], ahi[rt], blo);
            }
        }
    }

    // ---- epilogue ----
    // C layout: c0:(lr, 2lc) c1:(lr, 2lc+1) c2:(lr+8, 2lc) c3:(lr+8, 2lc+1)
    #pragma unroll
    for (int rt = 0; rt < 2; rt++) {
        #pragma unroll
        for (int half = 0; half < 2; half++) {
            int m = rt * 16 + half * 8 + lr;
            int node = nodeBase + m;
            if (node >= n_nodes) continue;
            int cnt = __ldg(g_cnt + node);
            cnt = max(0, min(cnt, CAP));
            float iv = (cnt > 0) ? __fdividef(1.0f, (float)cnt) : 1.0f;
            size_t ob = (size_t)node * 128;
            #pragma unroll
            for (int nt = 0; nt < 4; nt++) {
                float v0 = acc[rt][nt][half * 2 + 0] * iv;
                float v1 = acc[rt][nt][half * 2 + 1] * iv;
                int col = nt * 8 + 2 * lc;
                if (w == 0) {
                    *reinterpret_cast<float2*>(&out[ob + col]) =
                        make_float2(v0, v1);
                } else {
                    int b = 32 + (w - 1);
                    out[ob + b + 3 * col] = v0;
                    out[ob + b + 3 * (col + 1)] = v1;
                }
            }
        }
    }

    // ---- tail: self-clean counts for next graph replay ----
    __syncthreads();
    if (t < TILE_N) {
        int node = nodeBase + t;
        if (node < n_nodes) g_cnt[node] = 0;
    }
}

// --------------------------------------------------------------------------
// Launcher — exactly 2 kernels
// --------------------------------------------------------------------------
extern "C" void kernel_launch(void* const* d_in, const int* in_sizes, int n_in,
                              void* d_out, int out_size) {
    const float* nf   = (const float*)d_in[0];   // [N,128]
    const float* sh   = (const float*)d_in[1];   // [E,4]
    const int* senders   = (const int*)d_in[2];  // [E]
    const int* receivers = (const int*)d_in[3];  // [E]
    const float* W0  = (const float*)d_in[4];    // [96,32]
    const float* W1  = (const float*)d_in[5];    // [96,32]
    const float* Ws0 = (const float*)d_in[6];    // [32,32]
    const float* Ws1 = (const float*)d_in[7];    // [32,32]
    float* out = (float*)d_out;

    int n_nodes = in_sizes[0] / 128;
    int E = in_sizes[2];

    scatter_wprep_kernel<<<(E + 255) / 256, 256>>>(senders, receivers, sh, E,
                                                   W0, W1, Ws0, Ws1);

    int fb = (n_nodes + TILE_N - 1) / TILE_N;
    fused_kernel<<<fb, 128>>>(nf, out, n_nodes);
}

// round 16
// speedup vs baseline: 1.3346x; 1.0455x over previous
#include <cuda_runtime.h>
#include <cuda_bf16.h>
#include <cstdint>
#include <math.h>

#define N_MAX 50000
#define E_MAX 200000
#define TILE_N 32
#define CAP 40   // max in-degree slots per node (Poisson(4): P(>40) ~ 1e-38)

// Device scratch (no allocation allowed; zero-initialized at load,
// re-zeroed by fused_kernel at the end of every run => replay-safe)
__device__ int    g_cnt[N_MAX];
__device__ int    g_slot_send[N_MAX * CAP];     // 8 MB
__device__ float4 g_slot_sh[N_MAX * CAP];       // 32 MB
__device__ float  g_wc[2 * 96 * 32];            // combined weights [ch][k][v]

// m16n8k8 tf32 mma, row.col, fp32 accumulate
#define MMA_TF32(c, a, b) \
    asm("mma.sync.aligned.m16n8k8.row.col.f32.tf32.tf32.f32 " \
        "{%0,%1,%2,%3}, {%4,%5,%6,%7}, {%8,%9}, {%0,%1,%2,%3};" \
        : "+f"((c)[0]), "+f"((c)[1]), "+f"((c)[2]), "+f"((c)[3]) \
        : "r"((a)[0]), "r"((a)[1]), "r"((a)[2]), "r"((a)[3]), \
          "r"((b)[0]), "r"((b)[1]))

__device__ __forceinline__ void split_tf32(float x, uint32_t& hi, uint32_t& lo) {
    asm("cvt.rna.tf32.f32 %0, %1;" : "=r"(hi) : "f"(x));
    float r = x - __uint_as_float(hi);
    asm("cvt.rna.tf32.f32 %0, %1;" : "=r"(lo) : "f"(r));
}

// --------------------------------------------------------------------------
// Kernel 1: direct slot scatter + combined-weight prep (merged).
// Edge e: pos = atomicAdd(cnt[recv]); record -> slot[recv*CAP + pos].
// Threads idx < 6144 additionally build the combined weights:
//   ch0:   w[k][v] = W0[k][v]/(1.5*sqrt(96)) + (k<32 ? Ws0[k][v]/sqrt(32) : 0)
//   chvec: w[k][v] = W1[k][v]/(1.5*sqrt(96)) + (k<32 ? Ws1[k][v]/sqrt(32) : 0)
// --------------------------------------------------------------------------
__global__ void scatter_wprep_kernel(const int* __restrict__ send,
                                     const int* __restrict__ recv,
                                     const float* __restrict__ sh, int E,
                                     const float* __restrict__ W0,
                                     const float* __restrict__ W1,
                                     const float* __restrict__ Ws0,
                                     const float* __restrict__ Ws1) {
    int idx = blockIdx.x * blockDim.x + threadIdx.x;

    if (idx < 2 * 96 * 32) {
        const float c1 = 1.0f / (1.5f * 9.79795897113271f);  // 1/(1.5*sqrt(96))
        const float c2 = 1.0f / 5.656854249492381f;           // 1/sqrt(32)
        int ch = idx / (96 * 32);
        int rr = idx - ch * (96 * 32);
        int k = rr >> 5;
        const float* W  = ch ? W1  : W0;
        const float* Ws = ch ? Ws1 : Ws0;
        float val = W[rr] * c1;
        if (k < 32) val += Ws[rr] * c2;
        g_wc[idx] = val;
    }

    if (idx < E) {
        int r = recv[idx];
        if (r >= 0 && r < N_MAX) {
            int pos = atomicAdd(&g_cnt[r], 1);
            if (pos >= 0 && pos < CAP) {
                g_slot_send[r * CAP + pos] = send[idx];
                g_slot_sh[r * CAP + pos] =
                    __ldg(reinterpret_cast<const float4*>(sh) + idx);
            }
        }
    }
}

// --------------------------------------------------------------------------
// Kernel 2: fused gather + tensor-core GEMM. 256 threads, TILE_N=32 nodes.
// Phase 1 (gather): 8 warps, warp w owns nodes w*4..w*4+3; per node iterate
//   slots (deg = clamp(g_cnt)), accumulate 12 TP chains, store to swizzled
//   smem Xs[k][row]:
//     row = g*32+m (g=0 scalar, 1..3 = x/y/z), k = chain*32+u
//     chains: g0 [f0, s0*f0, dot/sqrt3]; g(1+c) [f1c, s0*f1c, f0*s1c]
//   index = k*128 + (row ^ ((k&7)<<2)).
// Phase 2 (GEMM): 3xTF32 mma.sync m16n8k8, 8 warps. Warp w: group g=w>>1,
//   row-half h=w&1 -> rows g*32+h*16 .. +15 (one m16 tile), 4 n-tiles,
//   12 k-steps. A from swizzled smem, B from g_wc via __ldg.
//   D = Ah*Bh + Al*Bh + Ah*Bl (~fp32). out[row][v] = (1/cnt)*D.
// Tail: t<32 zeroes g_cnt[node] (replay-safe). Static smem = exactly 48KB.
// --------------------------------------------------------------------------
__global__ void __launch_bounds__(256) fused_kernel(const float* __restrict__ nf,
                                                    float* __restrict__ out,
                                                    int n_nodes) {
    __shared__ float Xs[96 * 128];   // exactly 48KB
    const float INV_SQRT3 = 0.57735026918962576f;

    int t = threadIdx.x;
    int lane = t & 31;
    int w = t >> 5;               // 0..7
    int nodeBase = blockIdx.x * TILE_N;

    // ---- gather phase: 8 warps x 4 nodes ----
    #pragma unroll 1
    for (int mi = 0; mi < 4; mi++) {
        int m = w * 4 + mi;
        int i = nodeBase + m;
        if (i >= n_nodes) break;
        int deg = __ldg(g_cnt + i);
        deg = max(0, min(deg, CAP));

        float a0 = 0.f, a1 = 0.f, a2 = 0.f;   // g0: f0, s0*f0, dot
        float b0 = 0.f, b1 = 0.f, b2 = 0.f;   // gx: f1x, s0*f1x, f0*s1x
        float c0 = 0.f, c1 = 0.f, c2 = 0.f;   // gy
        float d0 = 0.f, d1 = 0.f, d2 = 0.f;   // gz

        const int*    slotS = g_slot_send + (size_t)i * CAP;
        const float4* slotH = g_slot_sh   + (size_t)i * CAP;

        for (int e = 0; e < deg; e++) {
            int s = __ldg(slotS + e);
            float4 shv = __ldg(slotH + e);
            const float* nfr = nf + 128 * s;
            float f0  = __ldg(nfr + lane);
            float f1x = __ldg(nfr + 32 + 3 * lane);
            float f1y = __ldg(nfr + 33 + 3 * lane);
            float f1z = __ldg(nfr + 34 + 3 * lane);

            a0 += f0;
            a1 = fmaf(shv.x, f0, a1);
            a2 += shv.y * f1x + shv.z * f1y + shv.w * f1z;
            b0 += f1x; b1 = fmaf(shv.x, f1x, b1); b2 = fmaf(f0, shv.y, b2);
            c0 += f1y; c1 = fmaf(shv.x, f1y, c1); c2 = fmaf(f0, shv.z, c2);
            d0 += f1z; d1 = fmaf(shv.x, f1z, d1); d2 = fmaf(f0, shv.w, d2);
        }
        a2 *= INV_SQRT3;

        // swizzled stores: c = (k&7)<<2, same for all 3 chains (k≡lane mod 32)
        int mc = m ^ ((lane & 7) << 2);
        float* X0 = Xs + lane * 128;          // chain0: k=lane
        X0[mc] = a0; X0[32 + mc] = b0; X0[64 + mc] = c0; X0[96 + mc] = d0;
        float* X1 = Xs + (32 + lane) * 128;   // chain1: k=32+lane
        X1[mc] = a1; X1[32 + mc] = b1; X1[64 + mc] = c1; X1[96 + mc] = d1;
        float* X2 = Xs + (64 + lane) * 128;   // chain2: k=64+lane
        X2[mc] = a2; X2[32 + mc] = b2; X2[64 + mc] = c2; X2[96 + mc] = d2;
    }
    __syncthreads();

    // ---- GEMM phase: 3xTF32 mma, 8 warps ----
    int g = w >> 1;               // group 0..3
    int h = w & 1;                // row-half within group
    const float* Wp = g_wc + ((g == 0) ? 0 : 96 * 32);
    int lr = lane >> 2;   // 0..7
    int lc = lane & 3;    // 0..3

    float acc[4][4];
    #pragma unroll
    for (int nt = 0; nt < 4; nt++)
        #pragma unroll
        for (int q = 0; q < 4; q++) acc[nt][q] = 0.f;

    #pragma unroll 2
    for (int ks = 0; ks < 12; ks++) {
        int k0 = ks * 8;
        // A fragment: m16n8k8 row-major: a_j: row = base + lr + (j&1)*8,
        //                                 k = k0 + lc + (j>>1)*4
        uint32_t ahi[4], alo[4];
        #pragma unroll
        for (int j = 0; j < 4; j++) {
            int row = g * 32 + h * 16 + lr + (j & 1) * 8;
            int k = k0 + lc + (j >> 1) * 4;
            float x = Xs[k * 128 + (row ^ ((k & 7) << 2))];
            split_tf32(x, ahi[j], alo[j]);
        }
        #pragma unroll
        for (int nt = 0; nt < 4; nt++) {
            // B fragment col-major 8x8: b_j: krow = k0+lc+j*4, col = nt*8+lr
            uint32_t bhi[2], blo[2];
            #pragma unroll
            for (int j = 0; j < 2; j++) {
                int krow = k0 + lc + j * 4;
                float v = __ldg(Wp + krow * 32 + nt * 8 + lr);
                split_tf32(v, bhi[j], blo[j]);
            }
            MMA_TF32(acc[nt], ahi, bhi);
            MMA_TF32(acc[nt], alo, bhi);
            MMA_TF32(acc[nt], ahi, blo);
        }
    }

    // ---- epilogue ----
    // C layout: c0:(lr, 2lc) c1:(lr, 2lc+1) c2:(lr+8, 2lc) c3:(lr+8, 2lc+1)
    #pragma unroll
    for (int half = 0; half < 2; half++) {
        int m = h * 16 + half * 8 + lr;      // node index within tile
        int node = nodeBase + m;
        if (node >= n_nodes) continue;
        int cnt = __ldg(g_cnt + node);
        cnt = max(0, min(cnt, CAP));
        float iv = (cnt > 0) ? __fdividef(1.0f, (float)cnt) : 1.0f;
        size_t ob = (size_t)node * 128;
        #pragma unroll
        for (int nt = 0; nt < 4; nt++) {
            float v0 = acc[nt][half * 2 + 0] * iv;
            float v1 = acc[nt][half * 2 + 1] * iv;
            int col = nt * 8 + 2 * lc;
            if (g == 0) {
                *reinterpret_cast<float2*>(&out[ob + col]) =
                    make_float2(v0, v1);
            } else {
                int b = 32 + (g - 1);
                out[ob + b + 3 * col] = v0;
                out[ob + b + 3 * (col + 1)] = v1;
            }
        }
    }

    // ---- tail: self-clean counts for next graph replay ----
    __syncthreads();
    if (t < TILE_N) {
        int node = nodeBase + t;
        if (node < n_nodes) g_cnt[node] = 0;
    }
}

// --------------------------------------------------------------------------
// Launcher — exactly 2 kernels
// --------------------------------------------------------------------------
extern "C" void kernel_launch(void* const* d_in, const int* in_sizes, int n_in,
                              void* d_out, int out_size) {
    const float* nf   = (const float*)d_in[0];   // [N,128]
    const float* sh   = (const float*)d_in[1];   // [E,4]
    const int* senders   = (const int*)d_in[2];  // [E]
    const int* receivers = (const int*)d_in[3];  // [E]
    const float* W0  = (const float*)d_in[4];    // [96,32]
    const float* W1  = (const float*)d_in[5];    // [96,32]
    const float* Ws0 = (const float*)d_in[6];    // [32,32]
    const float* Ws1 = (const float*)d_in[7];    // [32,32]
    float* out = (float*)d_out;

    int n_nodes = in_sizes[0] / 128;
    int E = in_sizes[2];

    scatter_wprep_kernel<<<(E + 255) / 256, 256>>>(senders, receivers, sh, E,
                                                   W0, W1, Ws0, Ws1);

    int fb = (n_nodes + TILE_N - 1) / TILE_N;
    fused_kernel<<<fb, 256>>>(nf, out, n_nodes);
}